// round 13
// baseline (speedup 1.0000x reference)
#include <cuda_runtime.h>
#include <cuda_fp16.h>
#include <cstdint>

// Problem constants
#define BB 8
#define SS 1024
#define DD 768
#define HH 12
#define HD 64

// Scratch (fp16): projected q,k (B,H,S,HD), v transposed (B,H,HD,S),
// e-scratch (B,H,S,S); fp32: rel_attn (B,S,S), row sums.
__device__ __half g_q[BB * HH * SS * HD];      // 12 MB
__device__ __half g_k[BB * HH * SS * HD];      // 12 MB
__device__ __half g_vT[BB * HH * HD * SS];     // 12 MB
__device__ __half g_e[(size_t)BB * HH * SS * SS];  // 201 MB
__device__ float  g_rel[BB * SS * SS];         // 32 MB
__device__ float  g_l[BB * HH * SS];           // 384 KB

// ---- fp16 mma helpers ------------------------------------------------------
__device__ __forceinline__ uint32_t pack_h2(float a, float b) {
    __half2 h = __floats2half2_rn(a, b);
    return *(uint32_t*)&h;
}
__device__ __forceinline__ uint2 pack2_h2(float4 v) {
    return make_uint2(pack_h2(v.x, v.y), pack_h2(v.z, v.w));
}
__device__ __forceinline__ float2 unpack_h2(uint32_t u) {
    __half2 h = *(__half2*)&u;
    return __half22float2(h);
}
// D(f32) += A(f16) * B(f16) : m16n8k16
__device__ __forceinline__ void mma16(float* d, const uint32_t* a, const uint32_t* b) {
    asm("mma.sync.aligned.m16n8k16.row.col.f32.f16.f16.f32 "
        "{%0,%1,%2,%3}, {%4,%5,%6,%7}, {%8,%9}, {%0,%1,%2,%3};"
        : "+f"(d[0]), "+f"(d[1]), "+f"(d[2]), "+f"(d[3])
        : "r"(a[0]), "r"(a[1]), "r"(a[2]), "r"(a[3]), "r"(b[0]), "r"(b[1]));
}

// ---------------------------------------------------------------------------
// Projection GEMM (fp16 MMA): Y[i,j] = sum_k X[i,k] * W[j,k] + b[j]
// Block 128x128, BK=32, double-buffered SMEM (1 barrier per 32-K),
// 8 warps (2x4), warp tile 64x32.
// vtFlag=0: write half (B,H,S,HD).  vtFlag=1: write half (B,H,HD,S).
// ---------------------------------------------------------------------------
__global__ __launch_bounds__(256) void proj_mma(
    const float* __restrict__ X, const float* __restrict__ W,
    const float* __restrict__ bias, __half* __restrict__ out, int vtFlag)
{
    // stride 20 h2-units: frag-read banks 20*grp+tig -> 32 distinct
    __shared__ uint32_t As[2][128][20];
    __shared__ uint32_t Bs[2][128][20];

    const int t    = threadIdx.x;
    const int lane = t & 31;
    const int wid  = t >> 5;
    const int grp  = lane >> 2;
    const int tig  = lane & 3;
    const int wm   = wid >> 2;         // 0..1
    const int wn   = wid & 3;          // 0..3
    const int bm   = blockIdx.y * 128;
    const int bn   = blockIdx.x * 128;

    float acc[4][4][4];
#pragma unroll
    for (int mt = 0; mt < 4; mt++)
#pragma unroll
        for (int nt = 0; nt < 4; nt++)
#pragma unroll
            for (int r = 0; r < 4; r++) acc[mt][nt][r] = 0.f;

    const int lr  = t >> 2;            // 0..63
    const int lcq = (t & 3) * 8;       // 0,8,16,24 (float col)
    const int c4  = (t & 3) * 4;       // h2 col
    const float* xp0 = X + (size_t)(bm + lr) * DD + lcq;
    const float* xp1 = xp0 + (size_t)64 * DD;
    const float* wp0 = W + (size_t)(bn + lr) * DD + lcq;
    const float* wp1 = wp0 + (size_t)64 * DD;

    float4 xa0a = *(const float4*)xp0, xa0b = *(const float4*)(xp0 + 4);
    float4 xa1a = *(const float4*)xp1, xa1b = *(const float4*)(xp1 + 4);
    float4 wb0a = *(const float4*)wp0, wb0b = *(const float4*)(wp0 + 4);
    float4 wb1a = *(const float4*)wp1, wb1b = *(const float4*)(wp1 + 4);

    int buf = 0;
    for (int k0 = 0; k0 < DD; k0 += 32, buf ^= 1) {
        {
            uint4 v;
            uint2 u0 = pack2_h2(xa0a), u1 = pack2_h2(xa0b);
            v = make_uint4(u0.x, u0.y, u1.x, u1.y);
            *(uint4*)&As[buf][lr][c4] = v;
            u0 = pack2_h2(xa1a); u1 = pack2_h2(xa1b);
            v = make_uint4(u0.x, u0.y, u1.x, u1.y);
            *(uint4*)&As[buf][lr + 64][c4] = v;
            u0 = pack2_h2(wb0a); u1 = pack2_h2(wb0b);
            v = make_uint4(u0.x, u0.y, u1.x, u1.y);
            *(uint4*)&Bs[buf][lr][c4] = v;
            u0 = pack2_h2(wb1a); u1 = pack2_h2(wb1b);
            v = make_uint4(u0.x, u0.y, u1.x, u1.y);
            *(uint4*)&Bs[buf][lr + 64][c4] = v;
        }
        if (k0 + 32 < DD) {
            xa0a = *(const float4*)(xp0 + k0 + 32);
            xa0b = *(const float4*)(xp0 + k0 + 36);
            xa1a = *(const float4*)(xp1 + k0 + 32);
            xa1b = *(const float4*)(xp1 + k0 + 36);
            wb0a = *(const float4*)(wp0 + k0 + 32);
            wb0b = *(const float4*)(wp0 + k0 + 36);
            wb1a = *(const float4*)(wp1 + k0 + 32);
            wb1b = *(const float4*)(wp1 + k0 + 36);
        }
        __syncthreads();

#pragma unroll
        for (int ks2 = 0; ks2 < 16; ks2 += 8) {
            uint32_t a[4][4], bq[4][2];
#pragma unroll
            for (int mt = 0; mt < 4; mt++) {
                const int m = wm * 64 + mt * 16;
                a[mt][0] = As[buf][m + grp][ks2 + tig];
                a[mt][1] = As[buf][m + grp + 8][ks2 + tig];
                a[mt][2] = As[buf][m + grp][ks2 + tig + 4];
                a[mt][3] = As[buf][m + grp + 8][ks2 + tig + 4];
            }
#pragma unroll
            for (int nt = 0; nt < 4; nt++) {
                const int n = wn * 32 + nt * 8;
                bq[nt][0] = Bs[buf][n + grp][ks2 + tig];
                bq[nt][1] = Bs[buf][n + grp][ks2 + tig + 4];
            }
#pragma unroll
            for (int mt = 0; mt < 4; mt++)
#pragma unroll
                for (int nt = 0; nt < 4; nt++)
                    mma16(acc[mt][nt], a[mt], bq[nt]);
        }
        // no trailing barrier: next STS targets the other buffer; reuse of this
        // buffer (k0+64) is ordered by the barrier of iteration k0+32.
    }

#pragma unroll
    for (int mt = 0; mt < 4; mt++) {
        const int row0 = bm + wm * 64 + mt * 16 + grp;
#pragma unroll
        for (int nt = 0; nt < 4; nt++) {
            const int col = bn + wn * 32 + nt * 8 + 2 * tig;
            const int h = col >> 6, d = col & 63;
            const float bi0 = bias[col], bi1 = bias[col + 1];
#pragma unroll
            for (int rr = 0; rr < 2; rr++) {
                const int row = row0 + 8 * rr;
                const int b = row >> 10, s = row & 1023;
                const float v0 = acc[mt][nt][2 * rr]     + bi0;
                const float v1 = acc[mt][nt][2 * rr + 1] + bi1;
                if (!vtFlag) {
                    *(uint32_t*)&out[(((size_t)b * HH + h) * SS + s) * HD + d] =
                        pack_h2(v0, v1);
                } else {
                    out[(((size_t)b * HH + h) * HD + d)     * SS + s] = __float2half(v0);
                    out[(((size_t)b * HH + h) * HD + d + 1) * SS + s] = __float2half(v1);
                }
            }
        }
    }
}

// ---------------------------------------------------------------------------
// rel_attn = softmax over k of (mask ? rel : -1e4).  (head-independent)
// ---------------------------------------------------------------------------
__global__ __launch_bounds__(256) void rel_softmax_kernel(
    const float* __restrict__ rel, const unsigned int* __restrict__ mask,
    float* __restrict__ outr)
{
    const int row = blockIdx.x;
    const float* r        = rel  + (size_t)row * SS;
    const unsigned int* m = mask + (size_t)row * SS;
    float* o              = outr + (size_t)row * SS;

    __shared__ float redmax[8], redsum[8];
    const int t = threadIdx.x;

    float v[4];
    float mx = -3.4e38f;
#pragma unroll
    for (int i = 0; i < 4; i++) {
        const int c = i * 256 + t;
        v[i] = m[c] ? r[c] : -1e4f;
        mx = fmaxf(mx, v[i]);
    }
#pragma unroll
    for (int o2 = 16; o2; o2 >>= 1) mx = fmaxf(mx, __shfl_xor_sync(0xffffffffu, mx, o2));
    if ((t & 31) == 0) redmax[t >> 5] = mx;
    __syncthreads();
    mx = redmax[0];
#pragma unroll
    for (int w = 1; w < 8; w++) mx = fmaxf(mx, redmax[w]);

    float sum = 0.f;
#pragma unroll
    for (int i = 0; i < 4; i++) {
        v[i] = __expf(v[i] - mx);
        sum += v[i];
    }
#pragma unroll
    for (int o2 = 16; o2; o2 >>= 1) sum += __shfl_xor_sync(0xffffffffu, sum, o2);
    if ((t & 31) == 0) redsum[t >> 5] = sum;
    __syncthreads();
    sum = 0.f;
#pragma unroll
    for (int w = 0; w < 8; w++) sum += redsum[w];
    const float inv = 1.f / sum;

#pragma unroll
    for (int i = 0; i < 4; i++) {
        const int c = i * 256 + t;
        o[c] = v[i] * inv;
    }
}

// ---------------------------------------------------------------------------
// QK (fp16 MMA): one block per (b, h, 128-q tile).
// Double-buffered K tiles + register prefetch: 1 barrier per kt.
// e = mask ? 0 : exp((q.k)/8); e -> g_e (fp16); row sums -> g_l.
// ---------------------------------------------------------------------------
#define QKS 36
#define QK_SMEM (3 * 128 * QKS * 4)

__global__ __launch_bounds__(256) void qk_mma(
    const __half* __restrict__ qg, const __half* __restrict__ kg,
    const unsigned int* __restrict__ mask,
    __half* __restrict__ eg, float* __restrict__ lsum)
{
    extern __shared__ uint32_t qsm[];
    uint32_t (*Qs)[QKS] = (uint32_t(*)[QKS])qsm;                 // [128][36]
    uint32_t* Kbuf = qsm + 128 * QKS;                            // 2 x [128][36]
    __shared__ float lsum_s[128];

    const int t    = threadIdx.x;
    const int lane = t & 31;
    const int wid  = t >> 5;
    const int grp  = lane >> 2;
    const int tig  = lane & 3;
    const int wm   = wid >> 2;
    const int wn   = wid & 3;
    const int qt = blockIdx.x, h = blockIdx.y, b = blockIdx.z;
    const int bh = b * HH + h;
    const int qbase = qt * 128;

    if (t < 128) lsum_s[t] = 0.f;

    // stage Q (128 x 64 halves = 128 x 32 h2)
    const uint4* Qg4 = (const uint4*)(qg + ((size_t)bh * SS + qbase) * HD);
#pragma unroll
    for (int i = 0; i < 4; i++) {
        const int f = t + 256 * i;
        const int r = f >> 3, c8 = (f & 7) * 4;
        *(uint4*)&Qs[r][c8] = Qg4[(size_t)r * 8 + (f & 7)];
    }

    const uint4* Kg4 = (const uint4*)(kg + (size_t)bh * SS * HD);
    float rs[4][2];
#pragma unroll
    for (int mt = 0; mt < 4; mt++) { rs[mt][0] = 0.f; rs[mt][1] = 0.f; }

    uint32_t* eg2 = (uint32_t*)eg;

    // prefetch K chunk 0
    uint4 kreg[4];
#pragma unroll
    for (int i = 0; i < 4; i++) {
        const int f = t + 256 * i;
        kreg[i] = Kg4[(size_t)(f >> 3) * 8 + (f & 7)];
    }

#pragma unroll 1
    for (int kt = 0; kt < 8; kt++) {
        uint32_t (*Ks)[QKS] = (uint32_t(*)[QKS])(Kbuf + (kt & 1) * 128 * QKS);
#pragma unroll
        for (int i = 0; i < 4; i++) {
            const int f = t + 256 * i;
            *(uint4*)&Ks[f >> 3][(f & 7) * 4] = kreg[i];
        }
        if (kt < 7) {
#pragma unroll
            for (int i = 0; i < 4; i++) {
                const int f = t + 256 * i;
                kreg[i] = Kg4[(size_t)((kt + 1) * 128 + (f >> 3)) * 8 + (f & 7)];
            }
        }
        __syncthreads();   // buf ready; also orders Qs/lsum_s on kt=0

        float acc[4][4][4];
#pragma unroll
        for (int mt = 0; mt < 4; mt++)
#pragma unroll
            for (int nt = 0; nt < 4; nt++)
#pragma unroll
                for (int r = 0; r < 4; r++) acc[mt][nt][r] = 0.f;

#pragma unroll
        for (int k16 = 0; k16 < 4; k16++) {
            const int ks2 = 8 * k16;
            uint32_t a[4][4], bq[4][2];
#pragma unroll
            for (int mt = 0; mt < 4; mt++) {
                const int m = wm * 64 + mt * 16;
                a[mt][0] = Qs[m + grp][ks2 + tig];
                a[mt][1] = Qs[m + grp + 8][ks2 + tig];
                a[mt][2] = Qs[m + grp][ks2 + tig + 4];
                a[mt][3] = Qs[m + grp + 8][ks2 + tig + 4];
            }
#pragma unroll
            for (int nt = 0; nt < 4; nt++) {
                const int n = wn * 32 + nt * 8;
                bq[nt][0] = Ks[n + grp][ks2 + tig];
                bq[nt][1] = Ks[n + grp][ks2 + tig + 4];
            }
#pragma unroll
            for (int mt = 0; mt < 4; mt++)
#pragma unroll
                for (int nt = 0; nt < 4; nt++)
                    mma16(acc[mt][nt], a[mt], bq[nt]);
        }

        // epilogue: mask, exp, store e (fp16), accumulate row sums
#pragma unroll
        for (int mt = 0; mt < 4; mt++) {
            const int q0 = qbase + wm * 64 + mt * 16 + grp;
#pragma unroll
            for (int nt = 0; nt < 4; nt++) {
                const int c = kt * 128 + wn * 32 + nt * 8 + 2 * tig;
                const uint2 ma = *(const uint2*)&mask[((size_t)b * SS + q0) * SS + c];
                const uint2 mb = *(const uint2*)&mask[((size_t)b * SS + q0 + 8) * SS + c];
                const float e00 = ma.x ? 0.f : __expf(acc[mt][nt][0] * 0.125f);
                const float e01 = ma.y ? 0.f : __expf(acc[mt][nt][1] * 0.125f);
                const float e10 = mb.x ? 0.f : __expf(acc[mt][nt][2] * 0.125f);
                const float e11 = mb.y ? 0.f : __expf(acc[mt][nt][3] * 0.125f);
                rs[mt][0] += e00 + e01;
                rs[mt][1] += e10 + e11;
                eg2[((size_t)bh * SS + q0) * (SS / 2) + (c >> 1)]     = pack_h2(e00, e01);
                eg2[((size_t)bh * SS + q0 + 8) * (SS / 2) + (c >> 1)] = pack_h2(e10, e11);
            }
        }
        // no trailing barrier: next STS goes to the other K buffer; reuse of
        // this buffer at kt+2 is ordered by the barrier at kt+1.
    }

    // reduce row sums: quad shuffle then smem atomics (4 n-warps share rows)
#pragma unroll
    for (int mt = 0; mt < 4; mt++)
#pragma unroll
        for (int rr = 0; rr < 2; rr++) {
            float v = rs[mt][rr];
            v += __shfl_xor_sync(0xffffffffu, v, 1);
            v += __shfl_xor_sync(0xffffffffu, v, 2);
            if (tig == 0)
                atomicAdd(&lsum_s[wm * 64 + mt * 16 + grp + 8 * rr], v);
        }
    __syncthreads();
    if (t < 128) lsum[(size_t)bh * SS + qbase + t] = lsum_s[t];
}

// ---------------------------------------------------------------------------
// PV (fp16 MMA): blend p = c0*e/l + l1*rel -> prob (fp32, mandatory output),
// stage P as fp16, O = P @ V with V from d-major fp16 g_vT.
// Double-buffered P/V tiles: 1 barrier per kt; V staged first so its LDG
// latency hides under the blend.
// ---------------------------------------------------------------------------
#define PVS 68
#define PV_SMEM ((2 * 128 + 2 * 64) * PVS * 4)

__global__ __launch_bounds__(256) void pv_mma(
    const float* __restrict__ lsum, const float* __restrict__ relattn,
    const __half* __restrict__ vT, const __half* __restrict__ eg,
    const float* __restrict__ l1p,
    float* __restrict__ out, float* __restrict__ prob)
{
    extern __shared__ uint32_t psm[];
    uint32_t* Pbuf = psm;                    // 2 x [128][68]
    uint32_t* Vbuf = psm + 2 * 128 * PVS;    // 2 x [64][68]
    __shared__ float invl_s[128];

    const int t    = threadIdx.x;
    const int lane = t & 31;
    const int wid  = t >> 5;
    const int grp  = lane >> 2;
    const int tig  = lane & 3;
    const int wm   = wid >> 2;
    const int wn   = wid & 3;
    const int qt = blockIdx.x, h = blockIdx.y, b = blockIdx.z;
    const int bh = b * HH + h;
    const int qbase = qt * 128;

    const float l1 = *l1p;
    const float c0 = 1.f - l1;

    if (t < 128) invl_s[t] = 1.f / lsum[(size_t)bh * SS + qbase + t];
    __syncthreads();

    const uint4* eg4 = (const uint4*)eg;
    const uint4* vT4 = (const uint4*)vT;

    float acc[4][2][4];
#pragma unroll
    for (int mt = 0; mt < 4; mt++)
#pragma unroll
        for (int nt = 0; nt < 2; nt++)
#pragma unroll
            for (int r = 0; r < 4; r++) acc[mt][nt][r] = 0.f;

#pragma unroll 1
    for (int kt = 0; kt < 8; kt++) {
        uint32_t (*Ps)[PVS] = (uint32_t(*)[PVS])(Pbuf + (kt & 1) * 128 * PVS);
        uint32_t (*Vs)[PVS] = (uint32_t(*)[PVS])(Vbuf + (kt & 1) * 64 * PVS);

        // stage V chunk first: [64 d][128 keys] — LDG latency hides under blend
#pragma unroll
        for (int i = 0; i < 4; i++) {
            const int f = t + 256 * i;            // 0..1023
            const int d = f >> 4, c16 = (f & 15) * 4;
            *(uint4*)&Vs[d][c16] =
                vT4[((size_t)bh * HD + d) * (SS / 8) + kt * 16 + (f & 15)];
        }
        // blend + prob write + stage P (128 q x 128 keys)
#pragma unroll
        for (int i = 0; i < 8; i++) {
            const int f = t + 256 * i;            // 0..2047
            const int r = f >> 4, c16 = (f & 15) * 4;   // h2 col 0..60
            const uint4 e4 = eg4[((size_t)bh * SS + qbase + r) * (SS / 8) + kt * 16 + (f & 15)];
            const float2 e0 = unpack_h2(e4.x);
            const float2 e1 = unpack_h2(e4.y);
            const float2 e2 = unpack_h2(e4.z);
            const float2 e3 = unpack_h2(e4.w);
            const float iv = invl_s[r];
            const float* rrow = relattn + ((size_t)b * SS + qbase + r) * SS + kt * 128 + c16 * 2;
            const float4 r0 = *(const float4*)rrow;
            const float4 r1 = *(const float4*)(rrow + 4);
            float4 p0, p1;
            p0.x = c0 * e0.x * iv + l1 * r0.x;
            p0.y = c0 * e0.y * iv + l1 * r0.y;
            p0.z = c0 * e1.x * iv + l1 * r0.z;
            p0.w = c0 * e1.y * iv + l1 * r0.w;
            p1.x = c0 * e2.x * iv + l1 * r1.x;
            p1.y = c0 * e2.y * iv + l1 * r1.y;
            p1.z = c0 * e3.x * iv + l1 * r1.z;
            p1.w = c0 * e3.y * iv + l1 * r1.w;
            float* prow = prob + ((size_t)bh * SS + qbase + r) * SS + kt * 128 + c16 * 2;
            *(float4*)prow       = p0;
            *(float4*)(prow + 4) = p1;
            uint4 ph;
            ph.x = pack_h2(p0.x, p0.y); ph.y = pack_h2(p0.z, p0.w);
            ph.z = pack_h2(p1.x, p1.y); ph.w = pack_h2(p1.z, p1.w);
            *(uint4*)&Ps[r][c16] = ph;
        }
        __syncthreads();   // buffers ready (also orders invl_s at kt=0)

#pragma unroll
        for (int k16 = 0; k16 < 8; k16++) {
            const int ks2 = 8 * k16;
            uint32_t a[4][4], bq[2][2];
#pragma unroll
            for (int mt = 0; mt < 4; mt++) {
                const int m = wm * 64 + mt * 16;
                a[mt][0] = Ps[m + grp][ks2 + tig];
                a[mt][1] = Ps[m + grp + 8][ks2 + tig];
                a[mt][2] = Ps[m + grp][ks2 + tig + 4];
                a[mt][3] = Ps[m + grp + 8][ks2 + tig + 4];
            }
#pragma unroll
            for (int nt = 0; nt < 2; nt++) {
                const int n = wn * 16 + nt * 8;
                bq[nt][0] = Vs[n + grp][ks2 + tig];
                bq[nt][1] = Vs[n + grp][ks2 + tig + 4];
            }
#pragma unroll
            for (int mt = 0; mt < 4; mt++)
#pragma unroll
                for (int nt = 0; nt < 2; nt++)
                    mma16(acc[mt][nt], a[mt], bq[nt]);
        }
        // no trailing barrier (double-buffered; see qk_mma note)
    }

#pragma unroll
    for (int mt = 0; mt < 4; mt++) {
        const int q0 = qbase + wm * 64 + mt * 16 + grp;
#pragma unroll
        for (int nt = 0; nt < 2; nt++) {
            const int d0 = wn * 16 + nt * 8 + 2 * tig;
            *(float2*)&out[((size_t)b * SS + q0) * DD + h * HD + d0] =
                make_float2(acc[mt][nt][0], acc[mt][nt][1]);
            *(float2*)&out[((size_t)b * SS + q0 + 8) * DD + h * HD + d0] =
                make_float2(acc[mt][nt][2], acc[mt][nt][3]);
        }
    }
}

// ---------------------------------------------------------------------------
extern "C" void kernel_launch(void* const* d_in, const int* in_sizes, int n_in,
                              void* d_out, int out_size)
{
    const float* query = (const float*)d_in[0];
    const float* key_t = (const float*)d_in[1];
    const float* value = (const float*)d_in[2];
    const float* rel   = (const float*)d_in[3];
    const unsigned int* mask = (const unsigned int*)d_in[4];
    const float* l1    = (const float*)d_in[5];
    const float* Wq = (const float*)d_in[6];
    const float* bq = (const float*)d_in[7];
    const float* Wk = (const float*)d_in[8];
    const float* bk = (const float*)d_in[9];
    const float* Wv = (const float*)d_in[10];
    const float* bv = (const float*)d_in[11];

    float* out  = (float*)d_out;
    float* prob = out + (size_t)BB * SS * DD;   // tuple layout: out, then prob_attn

    __half *pq, *pk, *pvT, *pe;
    float *prel, *pl;
    cudaGetSymbolAddress((void**)&pq,   g_q);
    cudaGetSymbolAddress((void**)&pk,   g_k);
    cudaGetSymbolAddress((void**)&pvT,  g_vT);
    cudaGetSymbolAddress((void**)&pe,   g_e);
    cudaGetSymbolAddress((void**)&prel, g_rel);
    cudaGetSymbolAddress((void**)&pl,   g_l);

    // one-time resources (created on the uncaptured correctness call)
    static cudaStream_t st[3];
    static cudaEvent_t evRoot, evK, evV, evR;
    static int inited = 0;
    if (!inited) {
        for (int i = 0; i < 3; i++)
            cudaStreamCreateWithFlags(&st[i], cudaStreamNonBlocking);
        cudaEventCreateWithFlags(&evRoot, cudaEventDisableTiming);
        cudaEventCreateWithFlags(&evK,    cudaEventDisableTiming);
        cudaEventCreateWithFlags(&evV,    cudaEventDisableTiming);
        cudaEventCreateWithFlags(&evR,    cudaEventDisableTiming);
        cudaFuncSetAttribute(qk_mma,
                             cudaFuncAttributeMaxDynamicSharedMemorySize, QK_SMEM);
        cudaFuncSetAttribute(pv_mma,
                             cudaFuncAttributeMaxDynamicSharedMemorySize, PV_SMEM);
        inited = 1;
    }

    // fork side streams off the capture-origin stream
    cudaEventRecord(evRoot, 0);
    cudaStreamWaitEvent(st[0], evRoot, 0);
    cudaStreamWaitEvent(st[1], evRoot, 0);
    cudaStreamWaitEvent(st[2], evRoot, 0);

    dim3 pg(DD / 128, (BB * SS) / 128);
    proj_mma<<<pg, 256>>>(query, Wq, bq, pq, 0);                 // default stream
    proj_mma<<<pg, 256, 0, st[0]>>>(key_t, Wk, bk, pk, 0);
    proj_mma<<<pg, 256, 0, st[1]>>>(value, Wv, bv, pvT, 1);
    rel_softmax_kernel<<<BB * SS, 256, 0, st[2]>>>(rel, mask, prel);

    cudaEventRecord(evK, st[0]);
    cudaEventRecord(evV, st[1]);
    cudaEventRecord(evR, st[2]);

    // join: qk needs q (default) + k
    cudaStreamWaitEvent(0, evK, 0);
    qk_mma<<<dim3(8, HH, BB), 256, QK_SMEM>>>(pq, pk, mask, pe, pl);

    // pv additionally needs v + rel
    cudaStreamWaitEvent(0, evV, 0);
    cudaStreamWaitEvent(0, evR, 0);
    pv_mma<<<dim3(8, HH, BB), 256, PV_SMEM>>>(pl, prel, pvT, pe, l1, out, prob);
}

// round 14
// speedup vs baseline: 1.4299x; 1.4299x over previous
#include <cuda_runtime.h>
#include <cuda_fp16.h>
#include <cstdint>

// Problem constants
#define BB 8
#define SS 1024
#define DD 768
#define HH 12
#define HD 64

// Scratch (fp16): projected q,k (B,H,S,HD), v transposed (B,H,HD,S),
// e-scratch (B,H,S,S); fp32: rel_attn (B,S,S), row sums.
__device__ __half g_q[BB * HH * SS * HD];      // 12 MB
__device__ __half g_k[BB * HH * SS * HD];      // 12 MB
__device__ __half g_vT[BB * HH * HD * SS];     // 12 MB
__device__ __half g_e[(size_t)BB * HH * SS * SS];  // 201 MB
__device__ float  g_rel[BB * SS * SS];         // 32 MB
__device__ float  g_l[BB * HH * SS];           // 384 KB

// ---- fp16 mma helpers ------------------------------------------------------
__device__ __forceinline__ uint32_t pack_h2(float a, float b) {
    __half2 h = __floats2half2_rn(a, b);
    return *(uint32_t*)&h;
}
__device__ __forceinline__ uint2 pack2_h2(float4 v) {
    return make_uint2(pack_h2(v.x, v.y), pack_h2(v.z, v.w));
}
__device__ __forceinline__ float2 unpack_h2(uint32_t u) {
    __half2 h = *(__half2*)&u;
    return __half22float2(h);
}
// D(f32) += A(f16) * B(f16) : m16n8k16
__device__ __forceinline__ void mma16(float* d, const uint32_t* a, const uint32_t* b) {
    asm("mma.sync.aligned.m16n8k16.row.col.f32.f16.f16.f32 "
        "{%0,%1,%2,%3}, {%4,%5,%6,%7}, {%8,%9}, {%0,%1,%2,%3};"
        : "+f"(d[0]), "+f"(d[1]), "+f"(d[2]), "+f"(d[3])
        : "r"(a[0]), "r"(a[1]), "r"(a[2]), "r"(a[3]), "r"(b[0]), "r"(b[1]));
}

// ---------------------------------------------------------------------------
// Projection GEMM (fp16 MMA): Y[i,j] = sum_k X[i,k] * W[j,k] + b[j]
// Block 128x128, BK=16 (one k16 step), 8 warps (2x4), warp tile 64x32.
// (R10-proven configuration: 12.3 KB SMEM, full occupancy.)
// ---------------------------------------------------------------------------
__global__ __launch_bounds__(256) void proj_mma(
    const float* __restrict__ X, const float* __restrict__ W,
    const float* __restrict__ bias, __half* __restrict__ out, int vtFlag)
{
    __shared__ uint32_t As[128][12];   // half2 units: 8 data + 4 pad
    __shared__ uint32_t Bs[128][12];

    const int t    = threadIdx.x;
    const int lane = t & 31;
    const int wid  = t >> 5;
    const int grp  = lane >> 2;
    const int tig  = lane & 3;
    const int wm   = wid >> 2;         // 0..1
    const int wn   = wid & 3;          // 0..3
    const int bm   = blockIdx.y * 128;
    const int bn   = blockIdx.x * 128;

    float acc[4][4][4];
#pragma unroll
    for (int mt = 0; mt < 4; mt++)
#pragma unroll
        for (int nt = 0; nt < 4; nt++)
#pragma unroll
            for (int r = 0; r < 4; r++) acc[mt][nt][r] = 0.f;

    const int lr  = t >> 2;            // 0..63
    const int lc  = (t & 3) * 4;       // 0,4,8,12
    const int lc2 = lc >> 1;           // half2 col
    const float* xp0 = X + (size_t)(bm + lr) * DD + lc;
    const float* xp1 = xp0 + (size_t)64 * DD;
    const float* wp0 = W + (size_t)(bn + lr) * DD + lc;
    const float* wp1 = wp0 + (size_t)64 * DD;

    float4 xa0 = *(const float4*)xp0;
    float4 xa1 = *(const float4*)xp1;
    float4 wb0 = *(const float4*)wp0;
    float4 wb1 = *(const float4*)wp1;

    for (int k0 = 0; k0 < DD; k0 += 16) {
        *(uint2*)&As[lr][lc2]      = pack2_h2(xa0);
        *(uint2*)&As[lr + 64][lc2] = pack2_h2(xa1);
        *(uint2*)&Bs[lr][lc2]      = pack2_h2(wb0);
        *(uint2*)&Bs[lr + 64][lc2] = pack2_h2(wb1);
        __syncthreads();

        if (k0 + 16 < DD) {
            xa0 = *(const float4*)(xp0 + k0 + 16);
            xa1 = *(const float4*)(xp1 + k0 + 16);
            wb0 = *(const float4*)(wp0 + k0 + 16);
            wb1 = *(const float4*)(wp1 + k0 + 16);
        }

        uint32_t a[4][4], bq[4][2];
#pragma unroll
        for (int mt = 0; mt < 4; mt++) {
            const int m = wm * 64 + mt * 16;
            a[mt][0] = As[m + grp][tig];
            a[mt][1] = As[m + grp + 8][tig];
            a[mt][2] = As[m + grp][tig + 4];
            a[mt][3] = As[m + grp + 8][tig + 4];
        }
#pragma unroll
        for (int nt = 0; nt < 4; nt++) {
            const int n = wn * 32 + nt * 8;
            bq[nt][0] = Bs[n + grp][tig];
            bq[nt][1] = Bs[n + grp][tig + 4];
        }
#pragma unroll
        for (int mt = 0; mt < 4; mt++)
#pragma unroll
            for (int nt = 0; nt < 4; nt++)
                mma16(acc[mt][nt], a[mt], bq[nt]);
        __syncthreads();
    }

#pragma unroll
    for (int mt = 0; mt < 4; mt++) {
        const int row0 = bm + wm * 64 + mt * 16 + grp;
#pragma unroll
        for (int nt = 0; nt < 4; nt++) {
            const int col = bn + wn * 32 + nt * 8 + 2 * tig;
            const int h = col >> 6, d = col & 63;
            const float bi0 = bias[col], bi1 = bias[col + 1];
#pragma unroll
            for (int rr = 0; rr < 2; rr++) {
                const int row = row0 + 8 * rr;
                const int b = row >> 10, s = row & 1023;
                const float v0 = acc[mt][nt][2 * rr]     + bi0;
                const float v1 = acc[mt][nt][2 * rr + 1] + bi1;
                if (!vtFlag) {
                    *(uint32_t*)&out[(((size_t)b * HH + h) * SS + s) * HD + d] =
                        pack_h2(v0, v1);
                } else {
                    out[(((size_t)b * HH + h) * HD + d)     * SS + s] = __float2half(v0);
                    out[(((size_t)b * HH + h) * HD + d + 1) * SS + s] = __float2half(v1);
                }
            }
        }
    }
}

// ---------------------------------------------------------------------------
// rel_attn = softmax over k of (mask ? rel : -1e4).  (head-independent)
// ---------------------------------------------------------------------------
__global__ __launch_bounds__(256) void rel_softmax_kernel(
    const float* __restrict__ rel, const unsigned int* __restrict__ mask,
    float* __restrict__ outr)
{
    const int row = blockIdx.x;
    const float* r        = rel  + (size_t)row * SS;
    const unsigned int* m = mask + (size_t)row * SS;
    float* o              = outr + (size_t)row * SS;

    __shared__ float redmax[8], redsum[8];
    const int t = threadIdx.x;

    float v[4];
    float mx = -3.4e38f;
#pragma unroll
    for (int i = 0; i < 4; i++) {
        const int c = i * 256 + t;
        v[i] = m[c] ? r[c] : -1e4f;
        mx = fmaxf(mx, v[i]);
    }
#pragma unroll
    for (int o2 = 16; o2; o2 >>= 1) mx = fmaxf(mx, __shfl_xor_sync(0xffffffffu, mx, o2));
    if ((t & 31) == 0) redmax[t >> 5] = mx;
    __syncthreads();
    mx = redmax[0];
#pragma unroll
    for (int w = 1; w < 8; w++) mx = fmaxf(mx, redmax[w]);

    float sum = 0.f;
#pragma unroll
    for (int i = 0; i < 4; i++) {
        v[i] = __expf(v[i] - mx);
        sum += v[i];
    }
#pragma unroll
    for (int o2 = 16; o2; o2 >>= 1) sum += __shfl_xor_sync(0xffffffffu, sum, o2);
    if ((t & 31) == 0) redsum[t >> 5] = sum;
    __syncthreads();
    sum = 0.f;
#pragma unroll
    for (int w = 0; w < 8; w++) sum += redsum[w];
    const float inv = 1.f / sum;

#pragma unroll
    for (int i = 0; i < 4; i++) {
        const int c = i * 256 + t;
        o[c] = v[i] * inv;
    }
}

// ---------------------------------------------------------------------------
// QK (fp16 MMA): one block per (b, h, 128-q tile).
// Double-buffered K tiles + register prefetch: 1 barrier per kt.
// SMEM 55.3 KB -> still 4 blocks/SM (221 KB < 228 KB): occupancy preserved.
// e = mask ? 0 : exp((q.k)/8); e -> g_e (fp16); row sums -> g_l.
// ---------------------------------------------------------------------------
#define QKS 36
#define QK_SMEM (3 * 128 * QKS * 4)

__global__ __launch_bounds__(256) void qk_mma(
    const __half* __restrict__ qg, const __half* __restrict__ kg,
    const unsigned int* __restrict__ mask,
    __half* __restrict__ eg, float* __restrict__ lsum)
{
    extern __shared__ uint32_t qsm[];
    uint32_t (*Qs)[QKS] = (uint32_t(*)[QKS])qsm;                 // [128][36]
    uint32_t* Kbuf = qsm + 128 * QKS;                            // 2 x [128][36]
    __shared__ float lsum_s[128];

    const int t    = threadIdx.x;
    const int lane = t & 31;
    const int wid  = t >> 5;
    const int grp  = lane >> 2;
    const int tig  = lane & 3;
    const int wm   = wid >> 2;
    const int wn   = wid & 3;
    const int qt = blockIdx.x, h = blockIdx.y, b = blockIdx.z;
    const int bh = b * HH + h;
    const int qbase = qt * 128;

    if (t < 128) lsum_s[t] = 0.f;

    // stage Q (128 x 64 halves = 128 x 32 h2)
    const uint4* Qg4 = (const uint4*)(qg + ((size_t)bh * SS + qbase) * HD);
#pragma unroll
    for (int i = 0; i < 4; i++) {
        const int f = t + 256 * i;
        const int r = f >> 3, c8 = (f & 7) * 4;
        *(uint4*)&Qs[r][c8] = Qg4[(size_t)r * 8 + (f & 7)];
    }

    const uint4* Kg4 = (const uint4*)(kg + (size_t)bh * SS * HD);
    float rs[4][2];
#pragma unroll
    for (int mt = 0; mt < 4; mt++) { rs[mt][0] = 0.f; rs[mt][1] = 0.f; }

    uint32_t* eg2 = (uint32_t*)eg;

    // prefetch K chunk 0
    uint4 kreg[4];
#pragma unroll
    for (int i = 0; i < 4; i++) {
        const int f = t + 256 * i;
        kreg[i] = Kg4[(size_t)(f >> 3) * 8 + (f & 7)];
    }

#pragma unroll 1
    for (int kt = 0; kt < 8; kt++) {
        uint32_t (*Ks)[QKS] = (uint32_t(*)[QKS])(Kbuf + (kt & 1) * 128 * QKS);
#pragma unroll
        for (int i = 0; i < 4; i++) {
            const int f = t + 256 * i;
            *(uint4*)&Ks[f >> 3][(f & 7) * 4] = kreg[i];
        }
        if (kt < 7) {
#pragma unroll
            for (int i = 0; i < 4; i++) {
                const int f = t + 256 * i;
                kreg[i] = Kg4[(size_t)((kt + 1) * 128 + (f >> 3)) * 8 + (f & 7)];
            }
        }
        __syncthreads();   // buf ready; also orders Qs/lsum_s on kt=0

        float acc[4][4][4];
#pragma unroll
        for (int mt = 0; mt < 4; mt++)
#pragma unroll
            for (int nt = 0; nt < 4; nt++)
#pragma unroll
                for (int r = 0; r < 4; r++) acc[mt][nt][r] = 0.f;

#pragma unroll
        for (int k16 = 0; k16 < 4; k16++) {
            const int ks2 = 8 * k16;
            uint32_t a[4][4], bq[4][2];
#pragma unroll
            for (int mt = 0; mt < 4; mt++) {
                const int m = wm * 64 + mt * 16;
                a[mt][0] = Qs[m + grp][ks2 + tig];
                a[mt][1] = Qs[m + grp + 8][ks2 + tig];
                a[mt][2] = Qs[m + grp][ks2 + tig + 4];
                a[mt][3] = Qs[m + grp + 8][ks2 + tig + 4];
            }
#pragma unroll
            for (int nt = 0; nt < 4; nt++) {
                const int n = wn * 32 + nt * 8;
                bq[nt][0] = Ks[n + grp][ks2 + tig];
                bq[nt][1] = Ks[n + grp][ks2 + tig + 4];
            }
#pragma unroll
            for (int mt = 0; mt < 4; mt++)
#pragma unroll
                for (int nt = 0; nt < 4; nt++)
                    mma16(acc[mt][nt], a[mt], bq[nt]);
        }

        // epilogue: mask, exp, store e (fp16), accumulate row sums
#pragma unroll
        for (int mt = 0; mt < 4; mt++) {
            const int q0 = qbase + wm * 64 + mt * 16 + grp;
#pragma unroll
            for (int nt = 0; nt < 4; nt++) {
                const int c = kt * 128 + wn * 32 + nt * 8 + 2 * tig;
                const uint2 ma = *(const uint2*)&mask[((size_t)b * SS + q0) * SS + c];
                const uint2 mb = *(const uint2*)&mask[((size_t)b * SS + q0 + 8) * SS + c];
                const float e00 = ma.x ? 0.f : __expf(acc[mt][nt][0] * 0.125f);
                const float e01 = ma.y ? 0.f : __expf(acc[mt][nt][1] * 0.125f);
                const float e10 = mb.x ? 0.f : __expf(acc[mt][nt][2] * 0.125f);
                const float e11 = mb.y ? 0.f : __expf(acc[mt][nt][3] * 0.125f);
                rs[mt][0] += e00 + e01;
                rs[mt][1] += e10 + e11;
                eg2[((size_t)bh * SS + q0) * (SS / 2) + (c >> 1)]     = pack_h2(e00, e01);
                eg2[((size_t)bh * SS + q0 + 8) * (SS / 2) + (c >> 1)] = pack_h2(e10, e11);
            }
        }
        // no trailing barrier: next STS targets the other K buffer; reuse of
        // this buffer at kt+2 is ordered by the barrier at kt+1.
    }

    // reduce row sums: quad shuffle then smem atomics (4 n-warps share rows)
#pragma unroll
    for (int mt = 0; mt < 4; mt++)
#pragma unroll
        for (int rr = 0; rr < 2; rr++) {
            float v = rs[mt][rr];
            v += __shfl_xor_sync(0xffffffffu, v, 1);
            v += __shfl_xor_sync(0xffffffffu, v, 2);
            if (tig == 0)
                atomicAdd(&lsum_s[wm * 64 + mt * 16 + grp + 8 * rr], v);
        }
    __syncthreads();
    if (t < 128) lsum[(size_t)bh * SS + qbase + t] = lsum_s[t];
}

// ---------------------------------------------------------------------------
// PV (fp16 MMA): blend p = c0*e/l + l1*rel -> prob (fp32, mandatory output),
// stage P as fp16, O = P @ V with V from d-major fp16 g_vT.
// (R10-proven single-buffered configuration: 52.2 KB, 4 blocks/SM.)
// ---------------------------------------------------------------------------
#define PVS 68
#define PV_SMEM ((128 + 64) * PVS * 4)

__global__ __launch_bounds__(256) void pv_mma(
    const float* __restrict__ lsum, const float* __restrict__ relattn,
    const __half* __restrict__ vT, const __half* __restrict__ eg,
    const float* __restrict__ l1p,
    float* __restrict__ out, float* __restrict__ prob)
{
    extern __shared__ uint32_t psm[];
    uint32_t (*Ps)[PVS] = (uint32_t(*)[PVS])psm;               // [128 q][64 h2 keys + pad]
    uint32_t (*Vs)[PVS] = (uint32_t(*)[PVS])(psm + 128 * PVS); // [64 d][64 h2 keys + pad]
    __shared__ float invl_s[128];

    const int t    = threadIdx.x;
    const int lane = t & 31;
    const int wid  = t >> 5;
    const int grp  = lane >> 2;
    const int tig  = lane & 3;
    const int wm   = wid >> 2;
    const int wn   = wid & 3;
    const int qt = blockIdx.x, h = blockIdx.y, b = blockIdx.z;
    const int bh = b * HH + h;
    const int qbase = qt * 128;

    const float l1 = *l1p;
    const float c0 = 1.f - l1;

    if (t < 128) invl_s[t] = 1.f / lsum[(size_t)bh * SS + qbase + t];
    __syncthreads();

    const uint4* eg4 = (const uint4*)eg;
    const uint4* vT4 = (const uint4*)vT;

    float acc[4][2][4];
#pragma unroll
    for (int mt = 0; mt < 4; mt++)
#pragma unroll
        for (int nt = 0; nt < 2; nt++)
#pragma unroll
            for (int r = 0; r < 4; r++) acc[mt][nt][r] = 0.f;

#pragma unroll 1
    for (int kt = 0; kt < 8; kt++) {
        if (kt) __syncthreads();
        // stage V chunk first: [64 d][128 keys] — LDG latency hides under blend
#pragma unroll
        for (int i = 0; i < 4; i++) {
            const int f = t + 256 * i;            // 0..1023
            const int d = f >> 4, c16 = (f & 15) * 4;
            *(uint4*)&Vs[d][c16] =
                vT4[((size_t)bh * HD + d) * (SS / 8) + kt * 16 + (f & 15)];
        }
        // blend + prob write + stage P (128 q x 128 keys)
#pragma unroll
        for (int i = 0; i < 8; i++) {
            const int f = t + 256 * i;            // 0..2047
            const int r = f >> 4, c16 = (f & 15) * 4;   // h2 col 0..60
            const uint4 e4 = eg4[((size_t)bh * SS + qbase + r) * (SS / 8) + kt * 16 + (f & 15)];
            const float2 e0 = unpack_h2(e4.x);
            const float2 e1 = unpack_h2(e4.y);
            const float2 e2 = unpack_h2(e4.z);
            const float2 e3 = unpack_h2(e4.w);
            const float iv = invl_s[r];
            const float* rrow = relattn + ((size_t)b * SS + qbase + r) * SS + kt * 128 + c16 * 2;
            const float4 r0 = *(const float4*)rrow;
            const float4 r1 = *(const float4*)(rrow + 4);
            float4 p0, p1;
            p0.x = c0 * e0.x * iv + l1 * r0.x;
            p0.y = c0 * e0.y * iv + l1 * r0.y;
            p0.z = c0 * e1.x * iv + l1 * r0.z;
            p0.w = c0 * e1.y * iv + l1 * r0.w;
            p1.x = c0 * e2.x * iv + l1 * r1.x;
            p1.y = c0 * e2.y * iv + l1 * r1.y;
            p1.z = c0 * e3.x * iv + l1 * r1.z;
            p1.w = c0 * e3.y * iv + l1 * r1.w;
            float* prow = prob + ((size_t)bh * SS + qbase + r) * SS + kt * 128 + c16 * 2;
            *(float4*)prow       = p0;
            *(float4*)(prow + 4) = p1;
            uint4 ph;
            ph.x = pack_h2(p0.x, p0.y); ph.y = pack_h2(p0.z, p0.w);
            ph.z = pack_h2(p1.x, p1.y); ph.w = pack_h2(p1.z, p1.w);
            *(uint4*)&Ps[r][c16] = ph;
        }
        __syncthreads();

#pragma unroll
        for (int k16 = 0; k16 < 8; k16++) {
            const int ks2 = 8 * k16;
            uint32_t a[4][4], bq[2][2];
#pragma unroll
            for (int mt = 0; mt < 4; mt++) {
                const int m = wm * 64 + mt * 16;
                a[mt][0] = Ps[m + grp][ks2 + tig];
                a[mt][1] = Ps[m + grp + 8][ks2 + tig];
                a[mt][2] = Ps[m + grp][ks2 + tig + 4];
                a[mt][3] = Ps[m + grp + 8][ks2 + tig + 4];
            }
#pragma unroll
            for (int nt = 0; nt < 2; nt++) {
                const int n = wn * 16 + nt * 8;
                bq[nt][0] = Vs[n + grp][ks2 + tig];
                bq[nt][1] = Vs[n + grp][ks2 + tig + 4];
            }
#pragma unroll
            for (int mt = 0; mt < 4; mt++)
#pragma unroll
                for (int nt = 0; nt < 2; nt++)
                    mma16(acc[mt][nt], a[mt], bq[nt]);
        }
    }

#pragma unroll
    for (int mt = 0; mt < 4; mt++) {
        const int q0 = qbase + wm * 64 + mt * 16 + grp;
#pragma unroll
        for (int nt = 0; nt < 2; nt++) {
            const int d0 = wn * 16 + nt * 8 + 2 * tig;
            *(float2*)&out[((size_t)b * SS + q0) * DD + h * HD + d0] =
                make_float2(acc[mt][nt][0], acc[mt][nt][1]);
            *(float2*)&out[((size_t)b * SS + q0 + 8) * DD + h * HD + d0] =
                make_float2(acc[mt][nt][2], acc[mt][nt][3]);
        }
    }
}

// ---------------------------------------------------------------------------
extern "C" void kernel_launch(void* const* d_in, const int* in_sizes, int n_in,
                              void* d_out, int out_size)
{
    const float* query = (const float*)d_in[0];
    const float* key_t = (const float*)d_in[1];
    const float* value = (const float*)d_in[2];
    const float* rel   = (const float*)d_in[3];
    const unsigned int* mask = (const unsigned int*)d_in[4];
    const float* l1    = (const float*)d_in[5];
    const float* Wq = (const float*)d_in[6];
    const float* bq = (const float*)d_in[7];
    const float* Wk = (const float*)d_in[8];
    const float* bk = (const float*)d_in[9];
    const float* Wv = (const float*)d_in[10];
    const float* bv = (const float*)d_in[11];

    float* out  = (float*)d_out;
    float* prob = out + (size_t)BB * SS * DD;   // tuple layout: out, then prob_attn

    __half *pq, *pk, *pvT, *pe;
    float *prel, *pl;
    cudaGetSymbolAddress((void**)&pq,   g_q);
    cudaGetSymbolAddress((void**)&pk,   g_k);
    cudaGetSymbolAddress((void**)&pvT,  g_vT);
    cudaGetSymbolAddress((void**)&pe,   g_e);
    cudaGetSymbolAddress((void**)&prel, g_rel);
    cudaGetSymbolAddress((void**)&pl,   g_l);

    // one-time resources (created on the uncaptured correctness call)
    static cudaStream_t st[3];
    static cudaEvent_t evRoot, evK, evV, evR;
    static int inited = 0;
    if (!inited) {
        for (int i = 0; i < 3; i++)
            cudaStreamCreateWithFlags(&st[i], cudaStreamNonBlocking);
        cudaEventCreateWithFlags(&evRoot, cudaEventDisableTiming);
        cudaEventCreateWithFlags(&evK,    cudaEventDisableTiming);
        cudaEventCreateWithFlags(&evV,    cudaEventDisableTiming);
        cudaEventCreateWithFlags(&evR,    cudaEventDisableTiming);
        cudaFuncSetAttribute(qk_mma,
                             cudaFuncAttributeMaxDynamicSharedMemorySize, QK_SMEM);
        cudaFuncSetAttribute(pv_mma,
                             cudaFuncAttributeMaxDynamicSharedMemorySize, PV_SMEM);
        inited = 1;
    }

    // fork side streams off the capture-origin stream
    cudaEventRecord(evRoot, 0);
    cudaStreamWaitEvent(st[0], evRoot, 0);
    cudaStreamWaitEvent(st[1], evRoot, 0);
    cudaStreamWaitEvent(st[2], evRoot, 0);

    dim3 pg(DD / 128, (BB * SS) / 128);
    proj_mma<<<pg, 256>>>(query, Wq, bq, pq, 0);                 // default stream
    proj_mma<<<pg, 256, 0, st[0]>>>(key_t, Wk, bk, pk, 0);
    proj_mma<<<pg, 256, 0, st[1]>>>(value, Wv, bv, pvT, 1);
    rel_softmax_kernel<<<BB * SS, 256, 0, st[2]>>>(rel, mask, prel);

    cudaEventRecord(evK, st[0]);
    cudaEventRecord(evV, st[1]);
    cudaEventRecord(evR, st[2]);

    // join: qk needs q (default) + k
    cudaStreamWaitEvent(0, evK, 0);
    qk_mma<<<dim3(8, HH, BB), 256, QK_SMEM>>>(pq, pk, mask, pe, pl);

    // pv additionally needs v + rel
    cudaStreamWaitEvent(0, evV, 0);
    cudaStreamWaitEvent(0, evR, 0);
    pv_mma<<<dim3(8, HH, BB), 256, PV_SMEM>>>(pl, prel, pvT, pe, l1, out, prob);
}